// round 2
// baseline (speedup 1.0000x reference)
#include <cuda_runtime.h>
#include <math_constants.h>

// Max-plus conv2d: out[b,o,h,w] = max_{c,ki,kj} x[b,c,h+ki-1,w+kj-1] + k[o,c,ki,kj]
// B=8, C=64, H=W=64, O=64, 3x3, stride 1, pad 1 (pad value = -inf).
//
// Compute-bound on fma(FADD)+alu(FMNMX) pipes. Tiling:
//   block: 64 threads, covers (b, 4 o, 8 h, 64 w). grid = 8*16*8 = 1024 blocks.
//   thread: 4 o x 8 w x 1 h -> 32 accumulators.
//   c loop in chunks of 8, x rows staged in smem, kernel slice staged once.

constexpr int Cc   = 64;   // channels
constexpr int Hc   = 64;
constexpr int Wc   = 64;
constexpr int Oc   = 64;
constexpr int OT   = 4;    // o per block
constexpr int HT   = 8;    // h per block
constexpr int CCH  = 8;    // c chunk
constexpr int XROWS = HT + 2;      // 10 input rows per tile
constexpr int XSTRIDE = 72;        // floats per smem row (16B aligned, col = ww + 4)
constexpr int SX_FLOATS = CCH * XROWS * XSTRIDE;   // 5760
constexpr int SK_FLOATS = Cc * 9 * OT;             // 2304

__global__ __launch_bounds__(64)
void maxplus_conv_kernel(const float* __restrict__ x,
                         const float* __restrict__ gk,
                         float* __restrict__ out)
{
    __shared__ __align__(16) float sx[SX_FLOATS];
    __shared__ __align__(16) float sk[SK_FLOATS];

    const int bid = blockIdx.x;
    const int ht  = bid & 7;          // 8 h-tiles
    const int ot  = (bid >> 3) & 15;  // 16 o-tiles
    const int b   = bid >> 7;         // 8 batches

    const int h_base = ht * HT;
    const int o_base = ot * OT;

    const int tid = threadIdx.x;      // 0..63
    const int wg  = tid & 7;          // w group
    const int hl  = tid >> 3;         // 0..7
    const int wb  = wg * 8;           // w base (multiple of 8)
    const int h   = h_base + hl;

    // ---- stage kernel slice once: sk[(c*9 + ki*3 + kj)*4 + oo] ----
    for (int idx = tid; idx < SK_FLOATS; idx += 64) {
        int oo   = idx & 3;
        int rest = idx >> 2;  // c*9 + ki*3 + kj, 0..575
        sk[idx] = gk[(o_base + oo) * (Cc * 9) + rest];
    }

    float acc[OT][8];
#pragma unroll
    for (int oo = 0; oo < OT; oo++)
#pragma unroll
        for (int t = 0; t < 8; t++)
            acc[oo][t] = -CUDART_INF_F;

    const float* xb_ptr = x + (size_t)b * Cc * Hc * Wc;

    for (int ch = 0; ch < Cc / CCH; ch++) {
        __syncthreads();
        // ---- stage x chunk: channels c0..c0+7, rows h_base-1 .. h_base+8 ----
        // smem col layout: col = ww + 4 (ww in [-4, 67]); col 3 (ww=-1) and
        // col 68 (ww=64) must be -inf; cols 0..2 / 69..71 are never consumed.
        const int c0 = ch * CCH;
        // interior: float4 per iter, 1280 vec elements total
        for (int idx = tid; idx < CCH * XROWS * 16; idx += 64) {
            int q  = idx & 15;        // 16 float4 per row
            int rw = idx >> 4;        // 0..79 = cl*10 + r
            int r  = rw % XROWS;
            int cl = rw / XROWS;
            int hh = h_base - 1 + r;
            float4 v;
            if (hh >= 0 && hh < Hc) {
                v = *(const float4*)(xb_ptr + ((size_t)(c0 + cl) * Hc + hh) * Wc + q * 4);
            } else {
                v = make_float4(-CUDART_INF_F, -CUDART_INF_F, -CUDART_INF_F, -CUDART_INF_F);
            }
            *(float4*)(sx + rw * XSTRIDE + 4 + q * 4) = v;
        }
        // borders: ww=-1 (col 3) and ww=64 (col 68)
        for (int rw = tid; rw < CCH * XROWS; rw += 64) {
            sx[rw * XSTRIDE + 3]  = -CUDART_INF_F;
            sx[rw * XSTRIDE + 68] = -CUDART_INF_F;
        }
        __syncthreads();

#pragma unroll 2
        for (int cl = 0; cl < CCH; cl++) {
            const int cg = c0 + cl;
#pragma unroll
            for (int ki = 0; ki < 3; ki++) {
                // x row for this (c, ki): need ww = wb-1 .. wb+8 -> cols wb+3 .. wb+12
                const float* xrow = sx + (cl * XROWS + hl + ki) * XSTRIDE;
                float xr[10];
                xr[0] = xrow[wb + 3];
                float4 va = *(const float4*)(xrow + wb + 4);
                float4 vb = *(const float4*)(xrow + wb + 8);
                xr[1] = va.x; xr[2] = va.y; xr[3] = va.z; xr[4] = va.w;
                xr[5] = vb.x; xr[6] = vb.y; xr[7] = vb.z; xr[8] = vb.w;
                xr[9] = xrow[wb + 12];

                // kernel taps: kv{kj}[oo], broadcast float4 loads
                const float4* kp = (const float4*)(sk + (cg * 9 + ki * 3) * 4);
                float4 kq0 = kp[0], kq1 = kp[1], kq2 = kp[2];
                float kv0[4] = {kq0.x, kq0.y, kq0.z, kq0.w};
                float kv1[4] = {kq1.x, kq1.y, kq1.z, kq1.w};
                float kv2[4] = {kq2.x, kq2.y, kq2.z, kq2.w};

#pragma unroll
                for (int oo = 0; oo < OT; oo++) {
                    float k0 = kv0[oo], k1 = kv1[oo], k2 = kv2[oo];
#pragma unroll
                    for (int t = 0; t < 8; t++) {
                        float a = acc[oo][t];
                        a = fmaxf(a, xr[t]     + k0);
                        a = fmaxf(a, xr[t + 1] + k1);
                        a = fmaxf(a, xr[t + 2] + k2);
                        acc[oo][t] = a;
                    }
                }
            }
        }
    }

    // ---- write out: out[b][o_base+oo][h][wb .. wb+7], 2x STG.128 per oo ----
    const size_t obase = (((size_t)b * Oc + o_base) * Hc + h) * Wc + wb;
#pragma unroll
    for (int oo = 0; oo < OT; oo++) {
        float4* p = (float4*)(out + obase + (size_t)oo * Hc * Wc);
        p[0] = make_float4(acc[oo][0], acc[oo][1], acc[oo][2], acc[oo][3]);
        p[1] = make_float4(acc[oo][4], acc[oo][5], acc[oo][6], acc[oo][7]);
    }
}

extern "C" void kernel_launch(void* const* d_in, const int* in_sizes, int n_in,
                              void* d_out, int out_size)
{
    const float* x  = (const float*)d_in[0];   // [8,64,64,64]
    const float* k  = (const float*)d_in[1];   // [64,64,3,3]
    float* out      = (float*)d_out;           // [8,64,64,64]
    (void)in_sizes; (void)n_in; (void)out_size;

    maxplus_conv_kernel<<<1024, 64>>>(x, k, out);
}

// round 5
// speedup vs baseline: 1.1551x; 1.1551x over previous
#include <cuda_runtime.h>
#include <math_constants.h>
#include <cstdint>

// Max-plus conv2d: out[b,o,h,w] = max_{c,ki,kj} x[b,c,h+ki-1,w+kj-1] + k[o,c,ki,kj]
// B=8, C=64, H=W=64, O=64, 3x3, stride 1, pad 1 (-inf).
//
// Issue-slot bound: 1 FADD + 1 FMNMX per (c,ki,kj,output) pair.
// Tiling: block = 64 threads = (b, 4 o, 8 h, 64 w); thread = 4o x 8w = 32 acc.
// c in chunks of 4, double-buffered in smem via cp.async (prefetch 1 chunk ahead).

constexpr int Cc  = 64;
constexpr int Hc  = 64;
constexpr int Wc  = 64;
constexpr int Oc  = 64;
constexpr int OT  = 4;
constexpr int HT  = 8;
constexpr int CCH = 4;              // channels per chunk
constexpr int NCH = Cc / CCH;       // 16 chunks
constexpr int XROWS   = HT + 2;     // 10
constexpr int XSTRIDE = 72;         // floats per smem row; col = w + 4
constexpr int XBUF    = CCH * XROWS * XSTRIDE;   // 2880 floats per stage
constexpr int SKF     = Cc * 9 * OT;             // 2304 floats

__device__ __forceinline__ void cp16(uint32_t s, const float* g) {
    asm volatile("cp.async.cg.shared.global [%0], [%1], 16;\n" :: "r"(s), "l"(g));
}
__device__ __forceinline__ void cp_commit() {
    asm volatile("cp.async.commit_group;\n" ::: "memory");
}
template <int N> __device__ __forceinline__ void cp_wait() {
    asm volatile("cp.async.wait_group %0;\n" :: "n"(N) : "memory");
}

__global__ __launch_bounds__(64)
void maxplus_conv_kernel(const float* __restrict__ x,
                         const float* __restrict__ gk,
                         float* __restrict__ out)
{
    __shared__ __align__(16) float sx[2 * XBUF];
    __shared__ __align__(16) float sk[SKF];

    const int bid = blockIdx.x;
    const int ht  = bid & 7;
    const int ot  = (bid >> 3) & 15;
    const int b   = bid >> 7;

    const int h_base = ht * HT;
    const int o_base = ot * OT;

    const int tid = threadIdx.x;
    const int wg  = tid & 7;
    const int hl  = tid >> 3;
    const int wb  = wg * 8;
    const int h   = h_base + hl;

    const uint32_t sx_u32 = (uint32_t)__cvta_generic_to_shared(sx);

    // ---- stage kernel slice once: sk[(c*9 + ki*3 + kj)*4 + oo] ----
    for (int idx = tid; idx < SKF; idx += 64) {
        int oo   = idx & 3;
        int rest = idx >> 2;
        sk[idx] = gk[(o_base + oo) * (Cc * 9) + rest];
    }

    // ---- prefill persistent -inf regions (cp.async never writes these) ----
    // border cols 3 (w=-1) and 68 (w=64), all rows, both buffers
    for (int rw = tid; rw < 2 * CCH * XROWS; rw += 64) {
        sx[rw * XSTRIDE + 3]  = -CUDART_INF_F;
        sx[rw * XSTRIDE + 68] = -CUDART_INF_F;
    }
    // invalid h rows (top tile: local row 0; bottom tile: local row 9), interior cols
    if (ht == 0 || ht == 7) {
        const int r = (ht == 0) ? 0 : (XROWS - 1);
        for (int i = tid; i < 2 * CCH * 16; i += 64) {   // buf x cl x 16 float4
            int q  = i & 15;
            int cl = (i >> 4) & 3;
            int bf = i >> 6;
            *(float4*)(sx + bf * XBUF + (cl * XROWS + r) * XSTRIDE + 4 + q * 4) =
                make_float4(-CUDART_INF_F, -CUDART_INF_F, -CUDART_INF_F, -CUDART_INF_F);
        }
    }

    // ---- async staging of one c-chunk into buffer bf ----
    const float* xb_base = x + (size_t)b * Cc * Hc * Wc;
    const int scl = tid >> 4;     // 0..3: channel within chunk
    const int sq  = tid & 15;     // float4 index within row

    auto stage = [&](int ch, int bf) {
        const int c0 = ch * CCH;
        uint32_t sdst = sx_u32 +
            (uint32_t)((bf * XBUF + (scl * XROWS) * XSTRIDE + 4 + sq * 4) * 4);
        const float* gsrc = xb_base + ((size_t)(c0 + scl) * Hc) * Wc + sq * 4;
#pragma unroll
        for (int j = 0; j < XROWS; j++) {
            int hh = h_base - 1 + j;
            if (hh >= 0 && hh < Hc)
                cp16(sdst + j * XSTRIDE * 4, gsrc + (size_t)hh * Wc);
        }
    };

    float acc[OT][8];
#pragma unroll
    for (int oo = 0; oo < OT; oo++)
#pragma unroll
        for (int t = 0; t < 8; t++)
            acc[oo][t] = -CUDART_INF_F;

    // prologue: prefetch chunk 0
    stage(0, 0);
    cp_commit();

#pragma unroll 1
    for (int ch = 0; ch < NCH; ch++) {
        const int bf = ch & 1;
        if (ch + 1 < NCH) {
            stage(ch + 1, bf ^ 1);   // buffer bf^1 freed by iter ch-1's end barrier
            cp_commit();
            cp_wait<1>();            // chunk ch's group complete
        } else {
            cp_wait<0>();
        }
        __syncthreads();

        // ---- compute chunk ch from buffer bf ----
        const float* xbase = sx + bf * XBUF + hl * XSTRIDE + wb;
        const float* kb    = sk + ch * (CCH * 36);
#pragma unroll 2
        for (int cl = 0; cl < CCH; cl++) {
#pragma unroll
            for (int ki = 0; ki < 3; ki++) {
                const float* xp = xbase + (cl * XROWS + ki) * XSTRIDE;
                float xr[10];
                xr[0] = xp[3];
                float4 va = *(const float4*)(xp + 4);
                float4 vb = *(const float4*)(xp + 8);
                xr[1] = va.x; xr[2] = va.y; xr[3] = va.z; xr[4] = va.w;
                xr[5] = vb.x; xr[6] = vb.y; xr[7] = vb.z; xr[8] = vb.w;
                xr[9] = xp[12];

                const float4* kp = (const float4*)(kb + cl * 36 + ki * 12);
                float4 kq0 = kp[0], kq1 = kp[1], kq2 = kp[2];
                float kv0[4] = {kq0.x, kq0.y, kq0.z, kq0.w};
                float kv1[4] = {kq1.x, kq1.y, kq1.z, kq1.w};
                float kv2[4] = {kq2.x, kq2.y, kq2.z, kq2.w};

#pragma unroll
                for (int oo = 0; oo < OT; oo++) {
                    float k0 = kv0[oo], k1 = kv1[oo], k2 = kv2[oo];
#pragma unroll
                    for (int t = 0; t < 8; t++) {
                        float a = acc[oo][t];
                        a = fmaxf(a, xr[t]     + k0);
                        a = fmaxf(a, xr[t + 1] + k1);
                        a = fmaxf(a, xr[t + 2] + k2);
                        acc[oo][t] = a;
                    }
                }
            }
        }
        __syncthreads();   // buffer bf may be overwritten at iter ch+1's stage()
    }

    // ---- write out: out[b][o_base+oo][h][wb..wb+7] ----
    const size_t obase = (((size_t)b * Oc + o_base) * Hc + h) * Wc + wb;
#pragma unroll
    for (int oo = 0; oo < OT; oo++) {
        float4* p = (float4*)(out + obase + (size_t)oo * Hc * Wc);
        p[0] = make_float4(acc[oo][0], acc[oo][1], acc[oo][2], acc[oo][3]);
        p[1] = make_float4(acc[oo][4], acc[oo][5], acc[oo][6], acc[oo][7]);
    }
}

extern "C" void kernel_launch(void* const* d_in, const int* in_sizes, int n_in,
                              void* d_out, int out_size)
{
    const float* x  = (const float*)d_in[0];   // [8,64,64,64]
    const float* k  = (const float*)d_in[1];   // [64,64,3,3]
    float* out      = (float*)d_out;           // [8,64,64,64]
    (void)in_sizes; (void)n_in; (void)out_size;

    maxplus_conv_kernel<<<1024, 64>>>(x, k, out);
}